// round 3
// baseline (speedup 1.0000x reference)
#include <cuda_runtime.h>
#include <stdint.h>

// Problem constants
#define BZ   32
#define SEQ  2048
#define D    768
#define P    16
#define PLACEHOLDER_ID 1
#define ROWS (BZ * SEQ)          // 65536
#define D4   (D / 4)             // 192 float4 per row

// ---------------------------------------------------------------------------
// Kernel A: per batch row (32 blocks x 256 threads):
//   1) find the P placeholder positions + their sequence rank (warp-shuffle scan)
//   2) cooperatively write prompt[rank] into out[...] for those rows.
// Runs BEFORE the gather; gather skips stores on placeholder rows.
// ---------------------------------------------------------------------------
__global__ __launch_bounds__(256)
void prompt_fill_kernel(const int* __restrict__ input_ids,
                        const float4* __restrict__ prompt,
                        float4* __restrict__ out) {
    const int row = blockIdx.x;                  // batch row 0..31
    const int* rid = input_ids + row * SEQ;
    const int t = threadIdx.x;
    const int lane = t & 31, warp = t >> 5;
    const int base = t * 8;

    int ids[8];
    int cnt = 0;
#pragma unroll
    for (int i = 0; i < 8; i++) {
        ids[i] = rid[base + i];
        cnt += (ids[i] == PLACEHOLDER_ID);
    }

    // inclusive warp scan of per-thread counts
    int inc = cnt;
#pragma unroll
    for (int off = 1; off < 32; off <<= 1) {
        int n = __shfl_up_sync(0xFFFFFFFFu, inc, off);
        if (lane >= off) inc += n;
    }

    __shared__ int wsum[8];
    __shared__ int s_pos[P];
    if (lane == 31) wsum[warp] = inc;
    __syncthreads();
    if (t == 0) {                                // exclusive scan of 8 warp sums
        int s = 0;
#pragma unroll
        for (int j = 0; j < 8; j++) { int x = wsum[j]; wsum[j] = s; s += x; }
    }
    __syncthreads();

    int rank = wsum[warp] + (inc - cnt);         // exclusive prefix for this thread
#pragma unroll
    for (int i = 0; i < 8; i++) {
        if (ids[i] == PLACEHOLDER_ID) {
            int r = rank < (P - 1) ? rank : (P - 1);
            s_pos[r] = base + i;                 // ranks are unique 0..15 (exactly P per row)
            rank++;
        }
    }
    __syncthreads();

    // cooperatively copy P prompt rows (16 x 3KB) to their output rows
    float4* orow = out + (size_t)row * SEQ * D4;
    for (int idx = t; idx < P * D4; idx += 256) {
        int r = idx / D4;
        int c = idx - r * D4;
        orow[(size_t)s_pos[r] * D4 + c] = __ldg(&prompt[r * D4 + c]);
    }
}

// ---------------------------------------------------------------------------
// Kernel B: main gather. 8192 blocks x 192 threads; each block handles 8
// consecutive output rows, one row per iteration (col == threadIdx.x).
// ids[i] == PLACEHOLDER_ID(=1) is a VALID emb row -> load unconditionally,
// just skip the store (row already holds prompt data from kernel A).
// All 8 gathers issued back-to-back (MLP=8); streaming stores keep the
// emb table L2-resident.
// ---------------------------------------------------------------------------
#define GTPB 192
#define RPB  8
#define GBLOCKS (ROWS / RPB)     // 8192

__global__ __launch_bounds__(GTPB)
void gather_rows_kernel(const int* __restrict__ input_ids,
                        const float4* __restrict__ emb,
                        float4* __restrict__ out) {
    const int r0 = blockIdx.x * RPB;
    const int t = threadIdx.x;

    int ids[RPB];
#pragma unroll
    for (int i = 0; i < RPB; i++)
        ids[i] = __ldg(&input_ids[r0 + i]);      // uniform per warp (broadcast)

    float4 v[RPB];
#pragma unroll
    for (int i = 0; i < RPB; i++)
        v[i] = __ldg(emb + (size_t)ids[i] * D4 + t);

#pragma unroll
    for (int i = 0; i < RPB; i++)
        if (ids[i] != PLACEHOLDER_ID)
            __stcs(out + (size_t)(r0 + i) * D4 + t, v[i]);
}

// ---------------------------------------------------------------------------
extern "C" void kernel_launch(void* const* d_in, const int* in_sizes, int n_in,
                              void* d_out, int out_size) {
    const int*    input_ids = (const int*)d_in[0];
    const float4* emb       = (const float4*)d_in[1];
    const float4* prompt    = (const float4*)d_in[2];
    float4*       out       = (float4*)d_out;

    prompt_fill_kernel<<<BZ, 256>>>(input_ids, prompt, out);
    gather_rows_kernel<<<GBLOCKS, GTPB>>>(input_ids, emb, out);
}

// round 4
// speedup vs baseline: 1.1230x; 1.1230x over previous
#include <cuda_runtime.h>
#include <stdint.h>

// Problem constants
#define BZ   32
#define SEQ  2048
#define D    768
#define P    16
#define PLACEHOLDER_ID 1
#define ROWS (BZ * SEQ)          // 65536
#define D4   (D / 4)             // 192 float4 per row

// ---------------------------------------------------------------------------
// Single fused kernel. 8192 blocks x 192 threads; block b handles 8
// consecutive rows of one batch row (RPB=8 divides SEQ, never crosses batch).
//
// Non-placeholder rows: gather emb[id] -> out (MLP=8 back-to-back LDG.128,
// streaming stores keep the 94MB emb table L2-resident).
// Placeholder rows (only ~494/8192 blocks see one): the block cooperatively
// counts placeholders in input_ids[batch, 0..seq0) to recover the rank, then
// stores prompt[min(rank,15)]. input_ids is 512KB and read by every block,
// so these extra reads are L2 hits.
// ---------------------------------------------------------------------------
#define GTPB 192
#define RPB  8
#define GBLOCKS (ROWS / RPB)     // 8192

__global__ __launch_bounds__(GTPB)
void fused_prompt_embed_kernel(const int* __restrict__ input_ids,
                               const float4* __restrict__ emb,
                               const float4* __restrict__ prompt,
                               float4* __restrict__ out) {
    const int r0    = blockIdx.x * RPB;
    const int t     = threadIdx.x;
    const int batch = r0 >> 11;              // r0 / SEQ
    const int seq0  = r0 & (SEQ - 1);
    const int* rid  = input_ids + ((size_t)batch << 11);

    int ids[RPB];
#pragma unroll
    for (int i = 0; i < RPB; i++)
        ids[i] = __ldg(&rid[seq0 + i]);      // uniform per block (broadcast)

    // Unconditional gathers: PLACEHOLDER_ID=1 is a valid emb row, the load is
    // harmless and keeps all 8 loads independent & back-to-back.
    float4 v[RPB];
#pragma unroll
    for (int i = 0; i < RPB; i++)
        v[i] = __ldg(emb + (size_t)ids[i] * D4 + t);

    bool anyph = false;
#pragma unroll
    for (int i = 0; i < RPB; i++) {
        if (ids[i] != PLACEHOLDER_ID)
            __stcs(out + (size_t)(r0 + i) * D4 + t, v[i]);
        anyph |= (ids[i] == PLACEHOLDER_ID);
    }

    if (!anyph) return;                      // block-uniform branch

    // ---- rare path: recover placeholder rank(s) for this block ----
    // count placeholders in rid[0 .. seq0)
    int cnt = 0;
    for (int j = t; j < seq0; j += GTPB)
        cnt += (__ldg(&rid[j]) == PLACEHOLDER_ID);

    __shared__ int s_sum;
    if (t == 0) s_sum = 0;
    __syncthreads();
#pragma unroll
    for (int off = 16; off > 0; off >>= 1)
        cnt += __shfl_down_sync(0xFFFFFFFFu, cnt, off);
    if ((t & 31) == 0) atomicAdd(&s_sum, cnt);
    __syncthreads();

    int rank = s_sum;                        // placeholders before seq0
#pragma unroll
    for (int i = 0; i < RPB; i++) {
        if (ids[i] == PLACEHOLDER_ID) {
            int r = rank < (P - 1) ? rank : (P - 1);
            __stcs(out + (size_t)(r0 + i) * D4 + t, __ldg(&prompt[r * D4 + t]));
            rank++;
        }
    }
}

// ---------------------------------------------------------------------------
extern "C" void kernel_launch(void* const* d_in, const int* in_sizes, int n_in,
                              void* d_out, int out_size) {
    const int*    input_ids = (const int*)d_in[0];
    const float4* emb       = (const float4*)d_in[1];
    const float4* prompt    = (const float4*)d_in[2];
    float4*       out       = (float4*)d_out;

    fused_prompt_embed_kernel<<<GBLOCKS, GTPB>>>(input_ids, emb, prompt, out);
}